// round 14
// baseline (speedup 1.0000x reference)
#include <cuda_runtime.h>
#include <cuda_bf16.h>
#include <math.h>
#include <stdint.h>

#define NB 4096
#define ND 128
#define NM 8192
#define NK 4
#define NBD (NB*ND)   /* 524288 */
#define KS6 768       /* 6 product-term blocks x 128, small->large order */

/* k_tc tiling: CTA 128x128, 4 warps (2M x 2N), warp tile 64x64, BK=32,
   2-stage cp.async, static smem 32KB -> occupancy 2 */
#define BM 128
#define BN 128
#define BK 32
#define TCTHREADS 128

/* ------------------------------------------------------------------ */
/* device scratch (static: allocation rules forbid cudaMalloc)         */
/* ------------------------------------------------------------------ */
__device__ float g_res[2*NBD];
__device__ float g_q[2*NBD];
__device__ float g_normX[2*NB];
__device__ float g_normE[NK*NM];
__device__ float g_dist[2*NB*NM];
__device__ __nv_bfloat16 g_Eb[(size_t)NK*NM*KS6];
__device__ __nv_bfloat16 g_Xp[(size_t)2*NB*KS6];
__device__ __nv_bfloat16 g_Xb[(size_t)NB*2*NM];
__device__ __nv_bfloat16 g_Yb[(size_t)NB*2*NM];
__device__ float g_S[(size_t)NB*NB];
__device__ unsigned long long g_amin[2*NB];
__device__ float g_cnt[2*NM];
__device__ unsigned g_minord;
__device__ float g_lr;
__device__ float g_mse[4];

/* ------------------------------------------------------------------ */
/* helpers                                                             */
/* ------------------------------------------------------------------ */
__device__ __forceinline__ float blockAllReduceSum(float v){
    __shared__ float sh[33];
    int lane = threadIdx.x & 31, w = threadIdx.x >> 5;
    __syncthreads();
    #pragma unroll
    for (int o=16;o>0;o>>=1) v += __shfl_down_sync(0xffffffffu, v, o);
    if (lane==0) sh[w] = v;
    __syncthreads();
    if (threadIdx.x==0){
        float s = 0.f; int nw = blockDim.x >> 5;
        for (int i=0;i<nw;i++) s += sh[i];
        sh[32] = s;
    }
    __syncthreads();
    return sh[32];
}
__device__ __forceinline__ float blockAllReduceMax(float v){
    __shared__ float sh[33];
    int lane = threadIdx.x & 31, w = threadIdx.x >> 5;
    __syncthreads();
    #pragma unroll
    for (int o=16;o>0;o>>=1) v = fmaxf(v, __shfl_down_sync(0xffffffffu, v, o));
    if (lane==0) sh[w] = v;
    __syncthreads();
    if (threadIdx.x==0){
        float s = -INFINITY; int nw = blockDim.x >> 5;
        for (int i=0;i<nw;i++) s = fmaxf(s, sh[i]);
        sh[32] = s;
    }
    __syncthreads();
    return sh[32];
}
__device__ __forceinline__ unsigned f2ord(float f){
    unsigned u = __float_as_uint(f);
    return (u >> 31) ? ~u : (u | 0x80000000u);
}
__device__ __forceinline__ float ord2f(unsigned o){
    unsigned u = (o >> 31) ? (o ^ 0x80000000u) : ~o;
    return __uint_as_float(u);
}
__device__ __forceinline__ void cp16(void* dst, const void* src){
    unsigned ds = (unsigned)__cvta_generic_to_shared(dst);
    asm volatile("cp.async.cg.shared.global [%0], [%1], 16;\n" :: "r"(ds), "l"(src));
}
__device__ __forceinline__ void ldm4(unsigned &r0,unsigned&r1,unsigned&r2,unsigned&r3,
                                     const void* p){
    unsigned a = (unsigned)__cvta_generic_to_shared(p);
    asm volatile("ldmatrix.sync.aligned.m8n8.x4.shared.b16 {%0,%1,%2,%3}, [%4];\n"
        : "=r"(r0),"=r"(r1),"=r"(r2),"=r"(r3) : "r"(a));
}
__device__ __forceinline__ void mma_bf16(float* d, const unsigned* a, const unsigned* b){
    asm volatile("mma.sync.aligned.m16n8k16.row.col.f32.bf16.bf16.f32 "
        "{%0,%1,%2,%3}, {%4,%5,%6,%7}, {%8,%9}, {%0,%1,%2,%3};\n"
        : "+f"(d[0]),"+f"(d[1]),"+f"(d[2]),"+f"(d[3])
        : "r"(a[0]),"r"(a[1]),"r"(a[2]),"r"(a[3]), "r"(b[0]),"r"(b[1]));
}

/* ------------------------------------------------------------------ */
__global__ void k_init(const float* __restrict__ pcf, const float* __restrict__ plm,
                       float* __restrict__ res, float* __restrict__ q,
                       unsigned* minord, float* lr, float* mse){
    int n = blockIdx.x*blockDim.x + threadIdx.x;
    if (n < 2*NBD){
        res[n] = (n < NBD) ? pcf[n] : plm[n - NBD];
        q[n] = 0.f;
    }
    if (n == 0){
        *minord = 0xFFFFFFFFu; *lr = 0.f;
        mse[0]=0.f; mse[1]=0.f; mse[2]=0.f; mse[3]=0.f;
    }
}

__global__ void k_rownorm(const float* __restrict__ x, float* __restrict__ out){
    int r = blockIdx.x;
    float v = x[(size_t)r*ND + threadIdx.x];
    float s = blockAllReduceSum(v*v);
    if (threadIdx.x==0) out[r] = s;
}

/* 3-plane bf16 split, product-term concat, SMALL->LARGE order (R11-validated):
   A: [h,m,m,l,h,h]  B: [m,h,m,h,l,h]  => hm+mh+mm+lh+hl+hh */
__global__ void k_splitA(const float* __restrict__ x, __nv_bfloat16* __restrict__ o){
    int r = blockIdx.x, t = threadIdx.x;
    float v = x[(size_t)r*ND + t];
    __nv_bfloat16 h = __float2bfloat16(v);
    float r1 = v - __bfloat162float(h);
    __nv_bfloat16 m = __float2bfloat16(r1);
    float r2 = r1 - __bfloat162float(m);
    __nv_bfloat16 l = __float2bfloat16(r2);
    size_t base = (size_t)r*KS6;
    o[base +   0 + t] = h;
    o[base + 128 + t] = m;
    o[base + 256 + t] = m;
    o[base + 384 + t] = l;
    o[base + 512 + t] = h;
    o[base + 640 + t] = h;
}
__global__ void k_splitB(const float* __restrict__ x, __nv_bfloat16* __restrict__ o){
    int r = blockIdx.x, t = threadIdx.x;
    float v = x[(size_t)r*ND + t];
    __nv_bfloat16 h = __float2bfloat16(v);
    float r1 = v - __bfloat162float(h);
    __nv_bfloat16 m = __float2bfloat16(r1);
    float r2 = r1 - __bfloat162float(m);
    __nv_bfloat16 l = __float2bfloat16(r2);
    size_t base = (size_t)r*KS6;
    o[base +   0 + t] = m;
    o[base + 128 + t] = h;
    o[base + 256 + t] = m;
    o[base + 384 + t] = h;
    o[base + 512 + t] = l;
    o[base + 640 + t] = h;
}

/* bf16 tensor-core NT GEMM: acc[i,j] = sum_k A[i,k]*B[j,k] (fp32 acc).
   CTA 128x128, 4 warps (2Mx2N), warp tile 64x64 (R13-validated fragments),
   BK=32, 2-stage cp.async (R11-validated structure), 32KB static smem, occ 2.
   blockIdx.z batches independent problems.
   mode 0: C = acc | mode 1: C = (nB+nA)-2acc | mode 2: fused argmin */
__global__ void __launch_bounds__(TCTHREADS,2) k_tc(
    const __nv_bfloat16* __restrict__ A, const __nv_bfloat16* __restrict__ B,
    float* __restrict__ C, int Kd, int Nc,
    const float* __restrict__ nA, const float* __restrict__ nB,
    unsigned long long* __restrict__ amin, int mode)
{
    __shared__ __align__(16) __nv_bfloat16 As[2][BM*BK];
    __shared__ __align__(16) __nv_bfloat16 Bs[2][BN*BK];

    const int t = threadIdx.x;
    const int lane = t & 31, warp = t >> 5;
    const int wm = warp & 1, wn = warp >> 1;   /* 2M x 2N */
    const int row0 = blockIdx.y*BM, col0 = blockIdx.x*BN;
    const int z = blockIdx.z;

    A    += (size_t)z*NB*Kd;
    if (nA)   nA   += (size_t)z*NB;
    if (amin) amin += (size_t)z*NB;
    if (mode==1) C += (size_t)z*NB*(size_t)Nc;

    float acc[4][8][4];
    #pragma unroll
    for (int i=0;i<4;i++)
        #pragma unroll
        for (int n=0;n<8;n++)
            #pragma unroll
            for (int x=0;x<4;x++) acc[i][n][x] = 0.f;

    auto prefetch = [&](int kb, int buf){
        size_t k0 = (size_t)kb*BK;
        int r = t;                              /* 128 threads = 128 rows */
        int sbase = (r>>1)&3;
        #pragma unroll
        for (int c1=0;c1<4;c1++){
            int s = c1 ^ sbase;
            cp16(&As[buf][r*BK + s*8], A + (size_t)(row0+r)*Kd + k0 + c1*8);
            cp16(&Bs[buf][r*BK + s*8], B + (size_t)(col0+r)*Kd + k0 + c1*8);
        }
    };

    const int nKb = Kd/BK;
    prefetch(0, 0);
    asm volatile("cp.async.commit_group;\n" ::);

    for (int kb=0; kb<nKb; ++kb){
        int buf = kb & 1;
        asm volatile("cp.async.wait_group 0;\n" ::);
        __syncthreads();
        if (kb+1 < nKb){
            prefetch(kb+1, buf^1);
            asm volatile("cp.async.commit_group;\n" ::);
        }
        #pragma unroll
        for (int ks=0; ks<2; ++ks){
            unsigned a[4][4];
            #pragma unroll
            for (int i=0;i<4;i++){
                int r  = wm*64 + i*16 + (lane & 15);
                int cb = ks*2 + (lane >> 4);
                ldm4(a[i][0],a[i][1],a[i][2],a[i][3],
                     &As[buf][r*BK + ((cb ^ ((r>>1)&3))<<3)]);
            }
            unsigned b[8][2];
            #pragma unroll
            for (int j=0;j<4;j++){
                int g  = lane >> 3;
                int r  = wn*64 + j*16 + (lane & 7) + ((g>>1)<<3);
                int cb = ks*2 + (g & 1);
                unsigned b0,b1,b2,b3;
                ldm4(b0,b1,b2,b3, &Bs[buf][r*BK + ((cb ^ ((r>>1)&3))<<3)]);
                b[2*j][0]=b0; b[2*j][1]=b1; b[2*j+1][0]=b2; b[2*j+1][1]=b3;
            }
            #pragma unroll
            for (int i=0;i<4;i++)
                #pragma unroll
                for (int n=0;n<8;n++)
                    mma_bf16(acc[i][n], a[i], b[n]);
        }
        __syncthreads();
    }

    if (mode == 2){
        /* fused argmin: 16 candidate cols/thread/row; first-index ties */
        #pragma unroll
        for (int i=0;i<4;i++){
            #pragma unroll
            for (int half=0; half<2; half++){
                int r = row0 + wm*64 + i*16 + (lane>>2) + half*8;
                float na = nA[r];
                float best = INFINITY; int bc = 0;
                #pragma unroll
                for (int n=0;n<8;n++){
                    #pragma unroll
                    for (int x=0;x<2;x++){
                        int c = col0 + wn*64 + n*8 + (lane&3)*2 + x;
                        float v = (nB[c] + na) - 2.0f*acc[i][n][half*2+x];
                        if (v < best){ best = v; bc = c; }
                    }
                }
                unsigned long long p =
                    ((unsigned long long)f2ord(best) << 32) | (unsigned)bc;
                unsigned long long q1 = __shfl_xor_sync(0xffffffffu, p, 1, 4);
                if (q1 < p) p = q1;
                unsigned long long q2 = __shfl_xor_sync(0xffffffffu, p, 2, 4);
                if (q2 < p) p = q2;
                if ((lane&3)==0) atomicMin(amin + r, p);
            }
        }
    } else if (mode == 1){
        #pragma unroll
        for (int i=0;i<4;i++){
            int r = row0 + wm*64 + i*16 + (lane>>2);
            float na  = nA[r];
            float na8 = nA[r+8];
            #pragma unroll
            for (int n=0;n<8;n++){
                int c = col0 + wn*64 + n*8 + (lane&3)*2;
                float v0 = (nB[c]   + na ) - 2.0f*acc[i][n][0];
                float v1 = (nB[c+1] + na ) - 2.0f*acc[i][n][1];
                float v2 = (nB[c]   + na8) - 2.0f*acc[i][n][2];
                float v3 = (nB[c+1] + na8) - 2.0f*acc[i][n][3];
                *(float2*)(C + (size_t)r*Nc + c)     = make_float2(v0, v1);
                *(float2*)(C + (size_t)(r+8)*Nc + c) = make_float2(v2, v3);
            }
        }
    } else {
        #pragma unroll
        for (int i=0;i<4;i++){
            int r = row0 + wm*64 + i*16 + (lane>>2);
            #pragma unroll
            for (int n=0;n<8;n++){
                int c = col0 + wn*64 + n*8 + (lane&3)*2;
                *(float2*)(C + (size_t)r*Nc + c)     = make_float2(acc[i][n][0], acc[i][n][1]);
                *(float2*)(C + (size_t)(r+8)*Nc + c) = make_float2(acc[i][n][2], acc[i][n][3]);
            }
        }
    }
}

/* fused per-stage init: amin sentinel + cnt zero (one launch, 16384 thr) */
__global__ void k_stageinit(unsigned long long* a, float* cnt){
    int i = blockIdx.x*blockDim.x + threadIdx.x;
    if (i < 2*NB) a[i] = 0xFFFFFFFFFFFFFFFFull;
    if (i < 2*NM) cnt[i] = 0.f;
}

__global__ void k_hist(const unsigned long long* __restrict__ amin, float* __restrict__ cnt){
    int s = blockIdx.y;
    int b = blockIdx.x*blockDim.x + threadIdx.x;
    int id = (int)(unsigned)(amin[s*NB + b] & 0xFFFFFFFFull);
    atomicAdd(cnt + s*NM + id, 1.0f);
}

__global__ void k_perp(const float* __restrict__ cnt, float* __restrict__ out_perp, int stage){
    int s = blockIdx.x, t = threadIdx.x;
    float acc = 0.f;
    for (int m=t;m<NM;m+=256){
        float avg = cnt[s*NM+m] * (1.0f/(float)NB);
        acc += avg * logf(avg + 1e-10f);
    }
    acc = blockAllReduceSum(acc);
    if (t==0) out_perp[stage*2 + s] = expf(-acc);
}

__global__ void k_update(const float* __restrict__ E, const unsigned long long* __restrict__ amin,
                         float* __restrict__ res, float* __restrict__ q,
                         float* __restrict__ out_sem, int stage){
    int s = blockIdx.y, b = blockIdx.x, t = threadIdx.x;
    int id = (int)(unsigned)(amin[s*NB + b] & 0xFFFFFFFFull);
    float e = E[(size_t)id*ND + t];
    size_t o = (size_t)s*NBD + (size_t)b*ND + t;
    res[o] -= e;
    q[o]   += e;
    if (t==0) out_sem[(size_t)s*NB*NK + (size_t)b*NK + stage] = (float)id;
}

__global__ void k_softmax(const float* __restrict__ dist,
                          __nv_bfloat16* __restrict__ X, __nv_bfloat16* __restrict__ Y){
    int s = blockIdx.y, b = blockIdx.x, t = threadIdx.x;
    const float* row = dist + ((size_t)s*NB + b)*NM;
    float z[32];
    float mx = -INFINITY;
    #pragma unroll
    for (int i=0;i<32;i++){
        float v = row[i*256 + t];
        v = -sqrtf(fmaxf(v, 0.f));
        z[i] = v;
        mx = fmaxf(mx, v);
    }
    mx = blockAllReduceMax(mx);
    float sm = 0.f;
    #pragma unroll
    for (int i=0;i<32;i++){
        float e = expf(z[i]-mx);
        z[i] = e; sm += e;
    }
    sm = blockAllReduceSum(sm);
    __nv_bfloat16* xr = X + (size_t)b*(2*NM) + (size_t)s*NM;
    __nv_bfloat16* yr = Y + (size_t)b*(2*NM) + (size_t)(1-s)*NM;
    #pragma unroll
    for (int i=0;i<32;i++){
        int m = i*256 + t;
        float ph = z[i]/sm;
        xr[m] = __float2bfloat16(ph);
        yr[m] = __float2bfloat16(logf(ph + 1e-10f));
    }
}

__global__ void k_minred(const float* __restrict__ S, unsigned* mo){
    size_t NN = (size_t)NB*NB;
    float best = INFINITY;
    for (size_t n = (size_t)blockIdx.x*blockDim.x + threadIdx.x; n < NN;
         n += (size_t)gridDim.x*blockDim.x)
        best = fminf(best, S[n]);
    __shared__ float sh[256];
    sh[threadIdx.x]=best; __syncthreads();
    for (int o=128;o>0;o>>=1){
        if (threadIdx.x<o) sh[threadIdx.x]=fminf(sh[threadIdx.x],sh[threadIdx.x+o]);
        __syncthreads();
    }
    if (threadIdx.x==0) atomicMin(mo, f2ord(sh[0]));
}

__global__ void k_ratio(const float* __restrict__ S, const unsigned* mo, float* lr){
    int i = blockIdx.x, t = threadIdx.x;
    float Max = -ord2f(*mo);
    const float* row = S + (size_t)i*NB;
    float sm = 0.f;
    for (int j=t;j<NB;j+=256) sm += expf(row[j] + Max);
    sm = blockAllReduceSum(sm);
    if (t==0){
        float diag = expf(row[i] + Max);
        float ratio = diag / (sm + 1e-5f);
        atomicAdd(lr, logf(ratio));
    }
}

__global__ void k_msequant(const float* __restrict__ pcf, const float* __restrict__ plm,
                           const float* __restrict__ q, float* __restrict__ out,
                           float* mse){
    int n = blockIdx.x*blockDim.x + threadIdx.x;
    float p  = pcf[n], pl = plm[n];
    float qp = q[n],   ql = q[NBD + n];
    float qzp = p  + (qp - p);
    float qzl = pl + (ql - pl);
    out[n]        = qzp;
    out[NBD + n]  = qzl;
    float d0 = p - qzp, d1 = p - qzl, d2 = pl - qzl, d3 = pl - qzp;
    float s0 = blockAllReduceSum(d0*d0);
    float s1 = blockAllReduceSum(d1*d1);
    float s2 = blockAllReduceSum(d2*d2);
    float s3 = blockAllReduceSum(d3*d3);
    if (threadIdx.x==0){
        atomicAdd(mse+0, s0); atomicAdd(mse+1, s1);
        atomicAdd(mse+2, s2); atomicAdd(mse+3, s3);
    }
}

__global__ void k_final(const float* lr, const float* mse, float* out_loss){
    float Lc = -(*lr) / (float)NB;
    float inv = 1.0f/(float)NBD;
    float pcf_loss = 0.25f*2.0f*(mse[0]*inv) + 0.25f*(mse[1]*inv);
    float plm_loss = 0.25f*2.0f*(mse[2]*inv) + 0.25f*(mse[3]*inv);
    *out_loss = 0.5f*Lc + pcf_loss + plm_loss;
}

/* ------------------------------------------------------------------ */
extern "C" void kernel_launch(void* const* d_in, const int* in_sizes, int n_in,
                              void* d_out, int out_size){
    const float* pcf = (const float*)d_in[0];
    const float* plm = (const float*)d_in[1];
    const float* emb = (const float*)d_in[2];
    float* out = (float*)d_out;

    void *p;
    float *res,*q,*normX,*normE,*dist,*S,*cnt,*lr,*mse;
    __nv_bfloat16 *Xb,*Yb,*Eb,*Xp;
    unsigned long long* amin;
    unsigned* mo;
    cudaGetSymbolAddress(&p, g_res);   res  = (float*)p;
    cudaGetSymbolAddress(&p, g_q);     q    = (float*)p;
    cudaGetSymbolAddress(&p, g_normX); normX= (float*)p;
    cudaGetSymbolAddress(&p, g_normE); normE= (float*)p;
    cudaGetSymbolAddress(&p, g_dist);  dist = (float*)p;
    cudaGetSymbolAddress(&p, g_Eb);    Eb   = (__nv_bfloat16*)p;
    cudaGetSymbolAddress(&p, g_Xp);    Xp   = (__nv_bfloat16*)p;
    cudaGetSymbolAddress(&p, g_Xb);    Xb   = (__nv_bfloat16*)p;
    cudaGetSymbolAddress(&p, g_Yb);    Yb   = (__nv_bfloat16*)p;
    cudaGetSymbolAddress(&p, g_S);     S    = (float*)p;
    cudaGetSymbolAddress(&p, g_amin);  amin = (unsigned long long*)p;
    cudaGetSymbolAddress(&p, g_cnt);   cnt  = (float*)p;
    cudaGetSymbolAddress(&p, g_minord);mo   = (unsigned*)p;
    cudaGetSymbolAddress(&p, g_lr);    lr   = (float*)p;
    cudaGetSymbolAddress(&p, g_mse);   mse  = (float*)p;

    /* output layout: quantized [2,B,D] | loss | sem_ids [2,B,K] | perp [K,2] */
    float* out_loss = out + (size_t)2*NBD;
    float* out_sem  = out_loss + 1;
    float* out_perp = out_sem + (size_t)2*NB*NK;

    k_init<<<(2*NBD+255)/256, 256>>>(pcf, plm, res, q, mo, lr, mse);
    k_splitB<<<NK*NM, 128>>>(emb, Eb);
    k_rownorm<<<NK*NM, 128>>>(emb, normE);
    k_rownorm<<<NB,128>>>(pcf, normX);
    k_rownorm<<<NB,128>>>(plm, normX+NB);
    k_splitA<<<2*NB, 128>>>(res, Xp);

    /* cmcm: only last stage's Lcmcm survives; ORIGINAL inputs + E3.
       z batches pcf/plm halves. */
    const __nv_bfloat16* Eb3 = Eb + (size_t)3*NM*KS6;
    k_tc<<<dim3(NM/BN, NB/BM, 2), TCTHREADS>>>(
        Xp, Eb3, dist, KS6, NM, normX, normE+3*NM, (unsigned long long*)0, 1);
    k_softmax<<<dim3(NB,2), 256>>>(dist, Xb, Yb);
    k_tc<<<dim3(NB/BN, NB/BM, 1), TCTHREADS>>>(
        Xb, Yb, S, 2*NM, NB, (const float*)0, (const float*)0, (unsigned long long*)0, 0);

    /* residual VQ stages: 6-term split bf16 dist GEMM with fused argmin */
    for (int st=0; st<NK; ++st){
        const float* E = emb + (size_t)st*NM*ND;
        const __nv_bfloat16* Ebs = Eb + (size_t)st*NM*KS6;
        if (st > 0){
            k_rownorm<<<NB,128>>>(res,      normX);
            k_rownorm<<<NB,128>>>(res+NBD,  normX+NB);
            k_splitA<<<2*NB, 128>>>(res, Xp);
        }
        k_stageinit<<<(2*NM+255)/256, 256>>>(amin, cnt);
        k_tc<<<dim3(NM/BN, NB/BM, 2), TCTHREADS>>>(
            Xp, Ebs, (float*)0, KS6, NM, normX, normE+st*NM, amin, 2);
        k_hist<<<dim3(NB/256,2),256>>>(amin, cnt);
        k_perp<<<2,256>>>(cnt, out_perp, st);
        k_update<<<dim3(NB,2),128>>>(E, amin, res, q, out_sem, st);
    }

    /* cmcm loss reductions */
    k_minred<<<4096,256>>>(S, mo);
    k_ratio<<<NB,256>>>(S, mo, lr);
    k_msequant<<<NBD/256,256>>>(pcf, plm, q, out, mse);
    k_final<<<1,1>>>(lr, mse, out_loss);
}

// round 15
// speedup vs baseline: 1.6667x; 1.6667x over previous
#include <cuda_runtime.h>
#include <cuda_bf16.h>
#include <math.h>
#include <stdint.h>

#define NB 4096
#define ND 128
#define NM 8192
#define NK 4
#define NBD (NB*ND)   /* 524288 */
#define KS6 768       /* 6 product-term blocks x 128, small->large order */

/* k_tc tiling: CTA 128x128, 8 warps (4M x 2N), warp tile 32x64, BK=32,
   3-stage cp.async with ONE barrier per iteration, 48KB static smem, occ 2 */
#define BM 128
#define BN 128
#define BK 32
#define SM_A (BM*BK)
#define SM_B (BN*BK)

/* ------------------------------------------------------------------ */
/* device scratch (static: allocation rules forbid cudaMalloc)         */
/* ------------------------------------------------------------------ */
__device__ float g_res[2*NBD];
__device__ float g_q[2*NBD];
__device__ float g_normX[2*NB];
__device__ float g_normE[NK*NM];
__device__ float g_dist[2*NB*NM];
__device__ __nv_bfloat16 g_Eb[(size_t)NK*NM*KS6];
__device__ __nv_bfloat16 g_Xp[(size_t)2*NB*KS6];
__device__ __nv_bfloat16 g_Xb[(size_t)NB*2*NM];
__device__ __nv_bfloat16 g_Yb[(size_t)NB*2*NM];
__device__ float g_S[(size_t)NB*NB];
__device__ unsigned long long g_amin[2*NB];
__device__ float g_cnt[2*NM];
__device__ unsigned g_minord;
__device__ float g_lr;
__device__ float g_mse[4];

/* ------------------------------------------------------------------ */
/* helpers                                                             */
/* ------------------------------------------------------------------ */
__device__ __forceinline__ float blockAllReduceSum(float v){
    __shared__ float sh[33];
    int lane = threadIdx.x & 31, w = threadIdx.x >> 5;
    __syncthreads();
    #pragma unroll
    for (int o=16;o>0;o>>=1) v += __shfl_down_sync(0xffffffffu, v, o);
    if (lane==0) sh[w] = v;
    __syncthreads();
    if (threadIdx.x==0){
        float s = 0.f; int nw = blockDim.x >> 5;
        for (int i=0;i<nw;i++) s += sh[i];
        sh[32] = s;
    }
    __syncthreads();
    return sh[32];
}
__device__ __forceinline__ float blockAllReduceMax(float v){
    __shared__ float sh[33];
    int lane = threadIdx.x & 31, w = threadIdx.x >> 5;
    __syncthreads();
    #pragma unroll
    for (int o=16;o>0;o>>=1) v = fmaxf(v, __shfl_down_sync(0xffffffffu, v, o));
    if (lane==0) sh[w] = v;
    __syncthreads();
    if (threadIdx.x==0){
        float s = -INFINITY; int nw = blockDim.x >> 5;
        for (int i=0;i<nw;i++) s = fmaxf(s, sh[i]);
        sh[32] = s;
    }
    __syncthreads();
    return sh[32];
}
__device__ __forceinline__ unsigned f2ord(float f){
    unsigned u = __float_as_uint(f);
    return (u >> 31) ? ~u : (u | 0x80000000u);
}
__device__ __forceinline__ float ord2f(unsigned o){
    unsigned u = (o >> 31) ? (o ^ 0x80000000u) : ~o;
    return __uint_as_float(u);
}
__device__ __forceinline__ void cp16(void* dst, const void* src){
    unsigned ds = (unsigned)__cvta_generic_to_shared(dst);
    asm volatile("cp.async.cg.shared.global [%0], [%1], 16;\n" :: "r"(ds), "l"(src));
}
__device__ __forceinline__ void ldm4(unsigned &r0,unsigned&r1,unsigned&r2,unsigned&r3,
                                     const void* p){
    unsigned a = (unsigned)__cvta_generic_to_shared(p);
    asm volatile("ldmatrix.sync.aligned.m8n8.x4.shared.b16 {%0,%1,%2,%3}, [%4];\n"
        : "=r"(r0),"=r"(r1),"=r"(r2),"=r"(r3) : "r"(a));
}
__device__ __forceinline__ void mma_bf16(float* d, const unsigned* a, const unsigned* b){
    asm volatile("mma.sync.aligned.m16n8k16.row.col.f32.bf16.bf16.f32 "
        "{%0,%1,%2,%3}, {%4,%5,%6,%7}, {%8,%9}, {%0,%1,%2,%3};\n"
        : "+f"(d[0]),"+f"(d[1]),"+f"(d[2]),"+f"(d[3])
        : "r"(a[0]),"r"(a[1]),"r"(a[2]),"r"(a[3]), "r"(b[0]),"r"(b[1]));
}

/* ------------------------------------------------------------------ */
__global__ void k_init(const float* __restrict__ pcf, const float* __restrict__ plm,
                       float* __restrict__ res, float* __restrict__ q,
                       unsigned* minord, float* lr, float* mse){
    int n = blockIdx.x*blockDim.x + threadIdx.x;
    if (n < 2*NBD){
        res[n] = (n < NBD) ? pcf[n] : plm[n - NBD];
        q[n] = 0.f;
    }
    if (n == 0){
        *minord = 0xFFFFFFFFu; *lr = 0.f;
        mse[0]=0.f; mse[1]=0.f; mse[2]=0.f; mse[3]=0.f;
    }
}

__global__ void k_rownorm(const float* __restrict__ x, float* __restrict__ out){
    int r = blockIdx.x;
    float v = x[(size_t)r*ND + threadIdx.x];
    float s = blockAllReduceSum(v*v);
    if (threadIdx.x==0) out[r] = s;
}

/* 3-plane bf16 split, product-term concat, SMALL->LARGE order (R11-validated):
   A: [h,m,m,l,h,h]  B: [m,h,m,h,l,h]  => hm+mh+mm+lh+hl+hh */
__global__ void k_splitA(const float* __restrict__ x, __nv_bfloat16* __restrict__ o){
    int r = blockIdx.x, t = threadIdx.x;
    float v = x[(size_t)r*ND + t];
    __nv_bfloat16 h = __float2bfloat16(v);
    float r1 = v - __bfloat162float(h);
    __nv_bfloat16 m = __float2bfloat16(r1);
    float r2 = r1 - __bfloat162float(m);
    __nv_bfloat16 l = __float2bfloat16(r2);
    size_t base = (size_t)r*KS6;
    o[base +   0 + t] = h;
    o[base + 128 + t] = m;
    o[base + 256 + t] = m;
    o[base + 384 + t] = l;
    o[base + 512 + t] = h;
    o[base + 640 + t] = h;
}
__global__ void k_splitB(const float* __restrict__ x, __nv_bfloat16* __restrict__ o){
    int r = blockIdx.x, t = threadIdx.x;
    float v = x[(size_t)r*ND + t];
    __nv_bfloat16 h = __float2bfloat16(v);
    float r1 = v - __bfloat162float(h);
    __nv_bfloat16 m = __float2bfloat16(r1);
    float r2 = r1 - __bfloat162float(m);
    __nv_bfloat16 l = __float2bfloat16(r2);
    size_t base = (size_t)r*KS6;
    o[base +   0 + t] = m;
    o[base + 128 + t] = h;
    o[base + 256 + t] = m;
    o[base + 384 + t] = h;
    o[base + 512 + t] = l;
    o[base + 640 + t] = h;
}

/* bf16 tensor-core NT GEMM: acc[i,j] = sum_k A[i,k]*B[j,k] (fp32 acc).
   R11-exact fragments: 8 warps (4M x 2N), warp tile 32x64.
   3-stage cp.async, ONE __syncthreads per K-iteration (R13-validated
   pipeline bookkeeping). blockIdx.z batches independent problems.
   mode 0: C = acc | mode 1: C = (nB+nA)-2acc | mode 2: fused argmin */
__global__ void __launch_bounds__(256,2) k_tc(
    const __nv_bfloat16* __restrict__ A, const __nv_bfloat16* __restrict__ B,
    float* __restrict__ C, int Kd, int Nc,
    const float* __restrict__ nA, const float* __restrict__ nB,
    unsigned long long* __restrict__ amin, int mode)
{
    __shared__ __align__(16) __nv_bfloat16 As[3][SM_A];
    __shared__ __align__(16) __nv_bfloat16 Bs[3][SM_B];

    const int t = threadIdx.x;
    const int lane = t & 31, warp = t >> 5;
    const int wm = warp & 3, wn = warp >> 2;   /* 4M x 2N, 32x64 warp tile */
    const int row0 = blockIdx.y*BM, col0 = blockIdx.x*BN;
    const int z = blockIdx.z;

    A    += (size_t)z*NB*Kd;
    if (nA)   nA   += (size_t)z*NB;
    if (amin) amin += (size_t)z*NB;
    if (mode==1) C += (size_t)z*NB*(size_t)Nc;

    float acc[2][8][4];
    #pragma unroll
    for (int i=0;i<2;i++)
        #pragma unroll
        for (int n=0;n<8;n++)
            #pragma unroll
            for (int x=0;x<4;x++) acc[i][n][x] = 0.f;

    auto prefetch = [&](int kb, int buf){
        size_t k0 = (size_t)kb*BK;
        int r1 = t>>2, c1 = t&3;
        int s1 = c1 ^ ((r1>>1)&3);
        cp16(&As[buf][r1*BK + s1*8], A + (size_t)(row0+r1)*Kd + k0 + c1*8);
        cp16(&Bs[buf][r1*BK + s1*8], B + (size_t)(col0+r1)*Kd + k0 + c1*8);
        int r2 = 64 + r1;
        int s2 = c1 ^ ((r2>>1)&3);
        cp16(&As[buf][r2*BK + s2*8], A + (size_t)(row0+r2)*Kd + k0 + c1*8);
        cp16(&Bs[buf][r2*BK + s2*8], B + (size_t)(col0+r2)*Kd + k0 + c1*8);
    };

    const int nKb = Kd/BK;   /* 24 (dist) or 512 (Scode) */
    prefetch(0, 0);
    asm volatile("cp.async.commit_group;\n" ::);
    prefetch(1, 1);
    asm volatile("cp.async.commit_group;\n" ::);

    int buf = 0;
    for (int kb=0; kb<nKb; ++kb){
        asm volatile("cp.async.wait_group 1;\n" ::);
        __syncthreads();
        /* top barrier doubles as: (a) buf data visible to all warps,
           (b) all warps done reading the buffer prefetch will overwrite
               (it was consumed in iteration kb-1). */
        if (kb+2 < nKb){
            int nb2 = buf+2; if (nb2 >= 3) nb2 -= 3;
            prefetch(kb+2, nb2);
            asm volatile("cp.async.commit_group;\n" ::);
        } else {
            asm volatile("cp.async.commit_group;\n" ::);  /* empty group keeps count */
        }
        const __nv_bfloat16* as = As[buf];
        const __nv_bfloat16* bs = Bs[buf];
        #pragma unroll
        for (int ks=0; ks<2; ++ks){
            unsigned a[2][4];
            #pragma unroll
            for (int i=0;i<2;i++){
                int r  = wm*32 + i*16 + (lane & 15);
                int cb = ks*2 + (lane >> 4);
                ldm4(a[i][0],a[i][1],a[i][2],a[i][3],
                     &as[r*BK + ((cb ^ ((r>>1)&3))<<3)]);
            }
            unsigned b[8][2];
            #pragma unroll
            for (int j=0;j<4;j++){
                int g  = lane >> 3;
                int r  = wn*64 + j*16 + (lane & 7) + ((g>>1)<<3);
                int cb = ks*2 + (g & 1);
                unsigned b0,b1,b2,b3;
                ldm4(b0,b1,b2,b3, &bs[r*BK + ((cb ^ ((r>>1)&3))<<3)]);
                b[2*j][0]=b0; b[2*j][1]=b1; b[2*j+1][0]=b2; b[2*j+1][1]=b3;
            }
            #pragma unroll
            for (int i=0;i<2;i++)
                #pragma unroll
                for (int n=0;n<8;n++)
                    mma_bf16(acc[i][n], a[i], b[n]);
        }
        buf = (buf+1 == 3) ? 0 : buf+1;
    }

    if (mode == 2){
        /* fused argmin: 16 candidate cols/thread/row; first-index ties */
        #pragma unroll
        for (int i=0;i<2;i++){
            #pragma unroll
            for (int half=0; half<2; half++){
                int r = row0 + wm*32 + i*16 + (lane>>2) + half*8;
                float na = nA[r];
                float best = INFINITY; int bc = 0;
                #pragma unroll
                for (int n=0;n<8;n++){
                    #pragma unroll
                    for (int x=0;x<2;x++){
                        int c = col0 + wn*64 + n*8 + (lane&3)*2 + x;
                        float v = (nB[c] + na) - 2.0f*acc[i][n][half*2+x];
                        if (v < best){ best = v; bc = c; }
                    }
                }
                unsigned long long p =
                    ((unsigned long long)f2ord(best) << 32) | (unsigned)bc;
                unsigned long long q1 = __shfl_xor_sync(0xffffffffu, p, 1, 4);
                if (q1 < p) p = q1;
                unsigned long long q2 = __shfl_xor_sync(0xffffffffu, p, 2, 4);
                if (q2 < p) p = q2;
                if ((lane&3)==0) atomicMin(amin + r, p);
            }
        }
    } else if (mode == 1){
        #pragma unroll
        for (int i=0;i<2;i++){
            int r = row0 + wm*32 + i*16 + (lane>>2);
            float na  = nA[r];
            float na8 = nA[r+8];
            #pragma unroll
            for (int n=0;n<8;n++){
                int c = col0 + wn*64 + n*8 + (lane&3)*2;
                float v0 = (nB[c]   + na ) - 2.0f*acc[i][n][0];
                float v1 = (nB[c+1] + na ) - 2.0f*acc[i][n][1];
                float v2 = (nB[c]   + na8) - 2.0f*acc[i][n][2];
                float v3 = (nB[c+1] + na8) - 2.0f*acc[i][n][3];
                *(float2*)(C + (size_t)r*Nc + c)     = make_float2(v0, v1);
                *(float2*)(C + (size_t)(r+8)*Nc + c) = make_float2(v2, v3);
            }
        }
    } else {
        #pragma unroll
        for (int i=0;i<2;i++){
            int r = row0 + wm*32 + i*16 + (lane>>2);
            #pragma unroll
            for (int n=0;n<8;n++){
                int c = col0 + wn*64 + n*8 + (lane&3)*2;
                *(float2*)(C + (size_t)r*Nc + c)     = make_float2(acc[i][n][0], acc[i][n][1]);
                *(float2*)(C + (size_t)(r+8)*Nc + c) = make_float2(acc[i][n][2], acc[i][n][3]);
            }
        }
    }
}

/* fused per-stage init: amin sentinel + cnt zero */
__global__ void k_stageinit(unsigned long long* a, float* cnt){
    int i = blockIdx.x*blockDim.x + threadIdx.x;
    if (i < 2*NB) a[i] = 0xFFFFFFFFFFFFFFFFull;
    if (i < 2*NM) cnt[i] = 0.f;
}

__global__ void k_hist(const unsigned long long* __restrict__ amin, float* __restrict__ cnt){
    int s = blockIdx.y;
    int b = blockIdx.x*blockDim.x + threadIdx.x;
    int id = (int)(unsigned)(amin[s*NB + b] & 0xFFFFFFFFull);
    atomicAdd(cnt + s*NM + id, 1.0f);
}

__global__ void k_perp(const float* __restrict__ cnt, float* __restrict__ out_perp, int stage){
    int s = blockIdx.x, t = threadIdx.x;
    float acc = 0.f;
    for (int m=t;m<NM;m+=256){
        float avg = cnt[s*NM+m] * (1.0f/(float)NB);
        acc += avg * logf(avg + 1e-10f);
    }
    acc = blockAllReduceSum(acc);
    if (t==0) out_perp[stage*2 + s] = expf(-acc);
}

__global__ void k_update(const float* __restrict__ E, const unsigned long long* __restrict__ amin,
                         float* __restrict__ res, float* __restrict__ q,
                         float* __restrict__ out_sem, int stage){
    int s = blockIdx.y, b = blockIdx.x, t = threadIdx.x;
    int id = (int)(unsigned)(amin[s*NB + b] & 0xFFFFFFFFull);
    float e = E[(size_t)id*ND + t];
    size_t o = (size_t)s*NBD + (size_t)b*ND + t;
    res[o] -= e;
    q[o]   += e;
    if (t==0) out_sem[(size_t)s*NB*NK + (size_t)b*NK + stage] = (float)id;
}

__global__ void k_softmax(const float* __restrict__ dist,
                          __nv_bfloat16* __restrict__ X, __nv_bfloat16* __restrict__ Y){
    int s = blockIdx.y, b = blockIdx.x, t = threadIdx.x;
    const float* row = dist + ((size_t)s*NB + b)*NM;
    float z[32];
    float mx = -INFINITY;
    #pragma unroll
    for (int i=0;i<32;i++){
        float v = row[i*256 + t];
        v = -sqrtf(fmaxf(v, 0.f));
        z[i] = v;
        mx = fmaxf(mx, v);
    }
    mx = blockAllReduceMax(mx);
    float sm = 0.f;
    #pragma unroll
    for (int i=0;i<32;i++){
        float e = expf(z[i]-mx);
        z[i] = e; sm += e;
    }
    sm = blockAllReduceSum(sm);
    __nv_bfloat16* xr = X + (size_t)b*(2*NM) + (size_t)s*NM;
    __nv_bfloat16* yr = Y + (size_t)b*(2*NM) + (size_t)(1-s)*NM;
    #pragma unroll
    for (int i=0;i<32;i++){
        int m = i*256 + t;
        float ph = z[i]/sm;
        xr[m] = __float2bfloat16(ph);
        yr[m] = __float2bfloat16(logf(ph + 1e-10f));
    }
}

__global__ void k_minred(const float* __restrict__ S, unsigned* mo){
    size_t NN = (size_t)NB*NB;
    float best = INFINITY;
    for (size_t n = (size_t)blockIdx.x*blockDim.x + threadIdx.x; n < NN;
         n += (size_t)gridDim.x*blockDim.x)
        best = fminf(best, S[n]);
    __shared__ float sh[256];
    sh[threadIdx.x]=best; __syncthreads();
    for (int o=128;o>0;o>>=1){
        if (threadIdx.x<o) sh[threadIdx.x]=fminf(sh[threadIdx.x],sh[threadIdx.x+o]);
        __syncthreads();
    }
    if (threadIdx.x==0) atomicMin(mo, f2ord(sh[0]));
}

__global__ void k_ratio(const float* __restrict__ S, const unsigned* mo, float* lr){
    int i = blockIdx.x, t = threadIdx.x;
    float Max = -ord2f(*mo);
    const float* row = S + (size_t)i*NB;
    float sm = 0.f;
    for (int j=t;j<NB;j+=256) sm += expf(row[j] + Max);
    sm = blockAllReduceSum(sm);
    if (t==0){
        float diag = expf(row[i] + Max);
        float ratio = diag / (sm + 1e-5f);
        atomicAdd(lr, logf(ratio));
    }
}

__global__ void k_msequant(const float* __restrict__ pcf, const float* __restrict__ plm,
                           const float* __restrict__ q, float* __restrict__ out,
                           float* mse){
    int n = blockIdx.x*blockDim.x + threadIdx.x;
    float p  = pcf[n], pl = plm[n];
    float qp = q[n],   ql = q[NBD + n];
    float qzp = p  + (qp - p);
    float qzl = pl + (ql - pl);
    out[n]        = qzp;
    out[NBD + n]  = qzl;
    float d0 = p - qzp, d1 = p - qzl, d2 = pl - qzl, d3 = pl - qzp;
    float s0 = blockAllReduceSum(d0*d0);
    float s1 = blockAllReduceSum(d1*d1);
    float s2 = blockAllReduceSum(d2*d2);
    float s3 = blockAllReduceSum(d3*d3);
    if (threadIdx.x==0){
        atomicAdd(mse+0, s0); atomicAdd(mse+1, s1);
        atomicAdd(mse+2, s2); atomicAdd(mse+3, s3);
    }
}

__global__ void k_final(const float* lr, const float* mse, float* out_loss){
    float Lc = -(*lr) / (float)NB;
    float inv = 1.0f/(float)NBD;
    float pcf_loss = 0.25f*2.0f*(mse[0]*inv) + 0.25f*(mse[1]*inv);
    float plm_loss = 0.25f*2.0f*(mse[2]*inv) + 0.25f*(mse[3]*inv);
    *out_loss = 0.5f*Lc + pcf_loss + plm_loss;
}

/* ------------------------------------------------------------------ */
extern "C" void kernel_launch(void* const* d_in, const int* in_sizes, int n_in,
                              void* d_out, int out_size){
    const float* pcf = (const float*)d_in[0];
    const float* plm = (const float*)d_in[1];
    const float* emb = (const float*)d_in[2];
    float* out = (float*)d_out;

    void *p;
    float *res,*q,*normX,*normE,*dist,*S,*cnt,*lr,*mse;
    __nv_bfloat16 *Xb,*Yb,*Eb,*Xp;
    unsigned long long* amin;
    unsigned* mo;
    cudaGetSymbolAddress(&p, g_res);   res  = (float*)p;
    cudaGetSymbolAddress(&p, g_q);     q    = (float*)p;
    cudaGetSymbolAddress(&p, g_normX); normX= (float*)p;
    cudaGetSymbolAddress(&p, g_normE); normE= (float*)p;
    cudaGetSymbolAddress(&p, g_dist);  dist = (float*)p;
    cudaGetSymbolAddress(&p, g_Eb);    Eb   = (__nv_bfloat16*)p;
    cudaGetSymbolAddress(&p, g_Xp);    Xp   = (__nv_bfloat16*)p;
    cudaGetSymbolAddress(&p, g_Xb);    Xb   = (__nv_bfloat16*)p;
    cudaGetSymbolAddress(&p, g_Yb);    Yb   = (__nv_bfloat16*)p;
    cudaGetSymbolAddress(&p, g_S);     S    = (float*)p;
    cudaGetSymbolAddress(&p, g_amin);  amin = (unsigned long long*)p;
    cudaGetSymbolAddress(&p, g_cnt);   cnt  = (float*)p;
    cudaGetSymbolAddress(&p, g_minord);mo   = (unsigned*)p;
    cudaGetSymbolAddress(&p, g_lr);    lr   = (float*)p;
    cudaGetSymbolAddress(&p, g_mse);   mse  = (float*)p;

    /* output layout: quantized [2,B,D] | loss | sem_ids [2,B,K] | perp [K,2] */
    float* out_loss = out + (size_t)2*NBD;
    float* out_sem  = out_loss + 1;
    float* out_perp = out_sem + (size_t)2*NB*NK;

    k_init<<<(2*NBD+255)/256, 256>>>(pcf, plm, res, q, mo, lr, mse);
    k_splitB<<<NK*NM, 128>>>(emb, Eb);
    k_rownorm<<<NK*NM, 128>>>(emb, normE);
    k_rownorm<<<NB,128>>>(pcf, normX);
    k_rownorm<<<NB,128>>>(plm, normX+NB);
    k_splitA<<<2*NB, 128>>>(res, Xp);

    /* cmcm: only last stage's Lcmcm survives; ORIGINAL inputs + E3.
       z batches pcf/plm halves. */
    const __nv_bfloat16* Eb3 = Eb + (size_t)3*NM*KS6;
    k_tc<<<dim3(NM/BN, NB/BM, 2), 256>>>(
        Xp, Eb3, dist, KS6, NM, normX, normE+3*NM, (unsigned long long*)0, 1);
    k_softmax<<<dim3(NB,2), 256>>>(dist, Xb, Yb);
    k_tc<<<dim3(NB/BN, NB/BM, 1), 256>>>(
        Xb, Yb, S, 2*NM, NB, (const float*)0, (const float*)0, (unsigned long long*)0, 0);

    /* residual VQ stages: 6-term split bf16 dist GEMM with fused argmin */
    for (int st=0; st<NK; ++st){
        const float* E = emb + (size_t)st*NM*ND;
        const __nv_bfloat16* Ebs = Eb + (size_t)st*NM*KS6;
        if (st > 0){
            k_rownorm<<<NB,128>>>(res,      normX);
            k_rownorm<<<NB,128>>>(res+NBD,  normX+NB);
            k_splitA<<<2*NB, 128>>>(res, Xp);
        }
        k_stageinit<<<(2*NM+255)/256, 256>>>(amin, cnt);
        k_tc<<<dim3(NM/BN, NB/BM, 2), 256>>>(
            Xp, Ebs, (float*)0, KS6, NM, normX, normE+st*NM, amin, 2);
        k_hist<<<dim3(NB/256,2),256>>>(amin, cnt);
        k_perp<<<2,256>>>(cnt, out_perp, st);
        k_update<<<dim3(NB,2),128>>>(E, amin, res, q, out_sem, st);
    }

    /* cmcm loss reductions */
    k_minred<<<4096,256>>>(S, mo);
    k_ratio<<<NB,256>>>(S, mo, lr);
    k_msequant<<<NBD/256,256>>>(pcf, plm, q, out, mse);
    k_final<<<1,1>>>(lr, mse, out_loss);
}

// round 16
// speedup vs baseline: 1.6804x; 1.0082x over previous
#include <cuda_runtime.h>
#include <cuda_bf16.h>
#include <math.h>
#include <stdint.h>

#define NB 4096
#define ND 128
#define NM 8192
#define NK 4
#define NBD (NB*ND)   /* 524288 */
#define KS6 768       /* 6 product-term blocks x 128, small->large order */

/* k_tc tiling: CTA 128x128, 8 warps (4M x 2N), warp tile 32x64, BK=64
   (two consecutive 128x32 subtiles per stage), 3-stage cp.async,
   ONE barrier per iteration, 96KB dynamic smem, occ 2 */
#define BM 128
#define BN 128
#define HALF (BM*32)          /* 4096 bf16 = one 128x32 subtile */
#define STG_A (2*HALF)        /* per-stage A = 8192 bf16 (16KB)  */
#define STG_B (2*HALF)        /* per-stage B = 8192 bf16 (16KB)  */
#define SMEM_BYTES (3*(STG_A+STG_B)*2)   /* 98304 */

/* ------------------------------------------------------------------ */
/* device scratch (static: allocation rules forbid cudaMalloc)         */
/* ------------------------------------------------------------------ */
__device__ float g_res[2*NBD];
__device__ float g_q[2*NBD];
__device__ float g_normX[2*NB];
__device__ float g_normE[NK*NM];
__device__ float g_dist[2*NB*NM];
__device__ __nv_bfloat16 g_Eb[(size_t)NK*NM*KS6];
__device__ __nv_bfloat16 g_Xp[(size_t)2*NB*KS6];
__device__ __nv_bfloat16 g_Xb[(size_t)NB*2*NM];
__device__ __nv_bfloat16 g_Yb[(size_t)NB*2*NM];
__device__ float g_S[(size_t)NB*NB];
__device__ unsigned long long g_amin[2*NB];
__device__ float g_cnt[2*NM];
__device__ unsigned g_minord;
__device__ float g_lr;
__device__ float g_mse[4];

/* ------------------------------------------------------------------ */
/* helpers                                                             */
/* ------------------------------------------------------------------ */
__device__ __forceinline__ float blockAllReduceSum(float v){
    __shared__ float sh[33];
    int lane = threadIdx.x & 31, w = threadIdx.x >> 5;
    __syncthreads();
    #pragma unroll
    for (int o=16;o>0;o>>=1) v += __shfl_down_sync(0xffffffffu, v, o);
    if (lane==0) sh[w] = v;
    __syncthreads();
    if (threadIdx.x==0){
        float s = 0.f; int nw = blockDim.x >> 5;
        for (int i=0;i<nw;i++) s += sh[i];
        sh[32] = s;
    }
    __syncthreads();
    return sh[32];
}
__device__ __forceinline__ float blockAllReduceMax(float v){
    __shared__ float sh[33];
    int lane = threadIdx.x & 31, w = threadIdx.x >> 5;
    __syncthreads();
    #pragma unroll
    for (int o=16;o>0;o>>=1) v = fmaxf(v, __shfl_down_sync(0xffffffffu, v, o));
    if (lane==0) sh[w] = v;
    __syncthreads();
    if (threadIdx.x==0){
        float s = -INFINITY; int nw = blockDim.x >> 5;
        for (int i=0;i<nw;i++) s = fmaxf(s, sh[i]);
        sh[32] = s;
    }
    __syncthreads();
    return sh[32];
}
__device__ __forceinline__ unsigned f2ord(float f){
    unsigned u = __float_as_uint(f);
    return (u >> 31) ? ~u : (u | 0x80000000u);
}
__device__ __forceinline__ float ord2f(unsigned o){
    unsigned u = (o >> 31) ? (o ^ 0x80000000u) : ~o;
    return __uint_as_float(u);
}
__device__ __forceinline__ void cp16(void* dst, const void* src){
    unsigned ds = (unsigned)__cvta_generic_to_shared(dst);
    asm volatile("cp.async.cg.shared.global [%0], [%1], 16;\n" :: "r"(ds), "l"(src));
}
__device__ __forceinline__ void ldm4(unsigned &r0,unsigned&r1,unsigned&r2,unsigned&r3,
                                     const void* p){
    unsigned a = (unsigned)__cvta_generic_to_shared(p);
    asm volatile("ldmatrix.sync.aligned.m8n8.x4.shared.b16 {%0,%1,%2,%3}, [%4];\n"
        : "=r"(r0),"=r"(r1),"=r"(r2),"=r"(r3) : "r"(a));
}
__device__ __forceinline__ void mma_bf16(float* d, const unsigned* a, const unsigned* b){
    asm volatile("mma.sync.aligned.m16n8k16.row.col.f32.bf16.bf16.f32 "
        "{%0,%1,%2,%3}, {%4,%5,%6,%7}, {%8,%9}, {%0,%1,%2,%3};\n"
        : "+f"(d[0]),"+f"(d[1]),"+f"(d[2]),"+f"(d[3])
        : "r"(a[0]),"r"(a[1]),"r"(a[2]),"r"(a[3]), "r"(b[0]),"r"(b[1]));
}

/* ------------------------------------------------------------------ */
__global__ void k_init(const float* __restrict__ pcf, const float* __restrict__ plm,
                       float* __restrict__ res, float* __restrict__ q,
                       unsigned* minord, float* lr, float* mse){
    int n = blockIdx.x*blockDim.x + threadIdx.x;
    if (n < 2*NBD){
        res[n] = (n < NBD) ? pcf[n] : plm[n - NBD];
        q[n] = 0.f;
    }
    if (n == 0){
        *minord = 0xFFFFFFFFu; *lr = 0.f;
        mse[0]=0.f; mse[1]=0.f; mse[2]=0.f; mse[3]=0.f;
    }
}

__global__ void k_rownorm(const float* __restrict__ x, float* __restrict__ out){
    int r = blockIdx.x;
    float v = x[(size_t)r*ND + threadIdx.x];
    float s = blockAllReduceSum(v*v);
    if (threadIdx.x==0) out[r] = s;
}

/* 3-plane bf16 split, product-term concat, SMALL->LARGE order (R11-validated):
   A: [h,m,m,l,h,h]  B: [m,h,m,h,l,h]  => hm+mh+mm+lh+hl+hh */
__global__ void k_splitA(const float* __restrict__ x, __nv_bfloat16* __restrict__ o){
    int r = blockIdx.x, t = threadIdx.x;
    float v = x[(size_t)r*ND + t];
    __nv_bfloat16 h = __float2bfloat16(v);
    float r1 = v - __bfloat162float(h);
    __nv_bfloat16 m = __float2bfloat16(r1);
    float r2 = r1 - __bfloat162float(m);
    __nv_bfloat16 l = __float2bfloat16(r2);
    size_t base = (size_t)r*KS6;
    o[base +   0 + t] = h;
    o[base + 128 + t] = m;
    o[base + 256 + t] = m;
    o[base + 384 + t] = l;
    o[base + 512 + t] = h;
    o[base + 640 + t] = h;
}
__global__ void k_splitB(const float* __restrict__ x, __nv_bfloat16* __restrict__ o){
    int r = blockIdx.x, t = threadIdx.x;
    float v = x[(size_t)r*ND + t];
    __nv_bfloat16 h = __float2bfloat16(v);
    float r1 = v - __bfloat162float(h);
    __nv_bfloat16 m = __float2bfloat16(r1);
    float r2 = r1 - __bfloat162float(m);
    __nv_bfloat16 l = __float2bfloat16(r2);
    size_t base = (size_t)r*KS6;
    o[base +   0 + t] = m;
    o[base + 128 + t] = h;
    o[base + 256 + t] = m;
    o[base + 384 + t] = h;
    o[base + 512 + t] = l;
    o[base + 640 + t] = h;
}

/* bf16 tensor-core NT GEMM: acc[i,j] = sum_k A[i,k]*B[j,k] (fp32 acc).
   R11-exact fragments (8 warps, 32x64 warp tile). BK=64 stored as two
   consecutive 128x32 subtiles (validated layout per half). 3-stage
   cp.async, one __syncthreads per iteration. z batches problems.
   mode 0: C = acc | mode 1: C = (nB+nA)-2acc | mode 2: fused argmin */
__global__ void __launch_bounds__(256,2) k_tc(
    const __nv_bfloat16* __restrict__ A, const __nv_bfloat16* __restrict__ B,
    float* __restrict__ C, int Kd, int Nc,
    const float* __restrict__ nA, const float* __restrict__ nB,
    unsigned long long* __restrict__ amin, int mode)
{
    extern __shared__ __align__(16) __nv_bfloat16 smbuf[];
    __nv_bfloat16* As = smbuf;                 /* 3 * STG_A */
    __nv_bfloat16* Bs = smbuf + 3*STG_A;       /* 3 * STG_B */

    const int t = threadIdx.x;
    const int lane = t & 31, warp = t >> 5;
    const int wm = warp & 3, wn = warp >> 2;   /* 4M x 2N, 32x64 warp tile */
    const int row0 = blockIdx.y*BM, col0 = blockIdx.x*BN;
    const int z = blockIdx.z;

    A    += (size_t)z*NB*Kd;
    if (nA)   nA   += (size_t)z*NB;
    if (amin) amin += (size_t)z*NB;
    if (mode==1) C += (size_t)z*NB*(size_t)Nc;

    float acc[2][8][4];
    #pragma unroll
    for (int i=0;i<2;i++)
        #pragma unroll
        for (int n=0;n<8;n++)
            #pragma unroll
            for (int x=0;x<4;x++) acc[i][n][x] = 0.f;

    auto prefetch = [&](int kb, int buf){
        int r1 = t>>2, c1 = t&3;
        int s1 = c1 ^ ((r1>>1)&3);
        int r2 = 64 + r1;
        int s2 = c1 ^ ((r2>>1)&3);
        #pragma unroll
        for (int half=0; half<2; half++){
            size_t k0 = (size_t)kb*64 + half*32;
            __nv_bfloat16* as = As + buf*STG_A + half*HALF;
            __nv_bfloat16* bs = Bs + buf*STG_B + half*HALF;
            cp16(&as[r1*32 + s1*8], A + (size_t)(row0+r1)*Kd + k0 + c1*8);
            cp16(&bs[r1*32 + s1*8], B + (size_t)(col0+r1)*Kd + k0 + c1*8);
            cp16(&as[r2*32 + s2*8], A + (size_t)(row0+r2)*Kd + k0 + c1*8);
            cp16(&bs[r2*32 + s2*8], B + (size_t)(col0+r2)*Kd + k0 + c1*8);
        }
    };

    const int nKb = Kd/64;   /* 12 (dist) or 256 (Scode) */
    prefetch(0, 0);
    asm volatile("cp.async.commit_group;\n" ::);
    prefetch(1, 1);
    asm volatile("cp.async.commit_group;\n" ::);

    int buf = 0;
    for (int kb=0; kb<nKb; ++kb){
        asm volatile("cp.async.wait_group 1;\n" ::);
        __syncthreads();
        /* top barrier doubles as: (a) buf data visible, (b) all warps done
           reading the buffer this prefetch overwrites (consumed at kb-1). */
        if (kb+2 < nKb){
            int nb2 = buf+2; if (nb2 >= 3) nb2 -= 3;
            prefetch(kb+2, nb2);
            asm volatile("cp.async.commit_group;\n" ::);
        } else {
            asm volatile("cp.async.commit_group;\n" ::);  /* empty group keeps count */
        }
        #pragma unroll
        for (int ks2=0; ks2<4; ++ks2){
            const int half = ks2 >> 1, ks = ks2 & 1;
            const __nv_bfloat16* as = As + buf*STG_A + half*HALF;
            const __nv_bfloat16* bs = Bs + buf*STG_B + half*HALF;
            unsigned a[2][4];
            #pragma unroll
            for (int i=0;i<2;i++){
                int r  = wm*32 + i*16 + (lane & 15);
                int cb = ks*2 + (lane >> 4);
                ldm4(a[i][0],a[i][1],a[i][2],a[i][3],
                     &as[r*32 + ((cb ^ ((r>>1)&3))<<3)]);
            }
            unsigned b[8][2];
            #pragma unroll
            for (int j=0;j<4;j++){
                int g  = lane >> 3;
                int r  = wn*64 + j*16 + (lane & 7) + ((g>>1)<<3);
                int cb = ks*2 + (g & 1);
                unsigned b0,b1,b2,b3;
                ldm4(b0,b1,b2,b3, &bs[r*32 + ((cb ^ ((r>>1)&3))<<3)]);
                b[2*j][0]=b0; b[2*j][1]=b1; b[2*j+1][0]=b2; b[2*j+1][1]=b3;
            }
            #pragma unroll
            for (int i=0;i<2;i++)
                #pragma unroll
                for (int n=0;n<8;n++)
                    mma_bf16(acc[i][n], a[i], b[n]);
        }
        buf = (buf+1 == 3) ? 0 : buf+1;
    }

    if (mode == 2){
        /* fused argmin: 16 candidate cols/thread/row; first-index ties */
        #pragma unroll
        for (int i=0;i<2;i++){
            #pragma unroll
            for (int half=0; half<2; half++){
                int r = row0 + wm*32 + i*16 + (lane>>2) + half*8;
                float na = nA[r];
                float best = INFINITY; int bc = 0;
                #pragma unroll
                for (int n=0;n<8;n++){
                    #pragma unroll
                    for (int x=0;x<2;x++){
                        int c = col0 + wn*64 + n*8 + (lane&3)*2 + x;
                        float v = (nB[c] + na) - 2.0f*acc[i][n][half*2+x];
                        if (v < best){ best = v; bc = c; }
                    }
                }
                unsigned long long p =
                    ((unsigned long long)f2ord(best) << 32) | (unsigned)bc;
                unsigned long long q1 = __shfl_xor_sync(0xffffffffu, p, 1, 4);
                if (q1 < p) p = q1;
                unsigned long long q2 = __shfl_xor_sync(0xffffffffu, p, 2, 4);
                if (q2 < p) p = q2;
                if ((lane&3)==0) atomicMin(amin + r, p);
            }
        }
    } else if (mode == 1){
        #pragma unroll
        for (int i=0;i<2;i++){
            int r = row0 + wm*32 + i*16 + (lane>>2);
            float na  = nA[r];
            float na8 = nA[r+8];
            #pragma unroll
            for (int n=0;n<8;n++){
                int c = col0 + wn*64 + n*8 + (lane&3)*2;
                float v0 = (nB[c]   + na ) - 2.0f*acc[i][n][0];
                float v1 = (nB[c+1] + na ) - 2.0f*acc[i][n][1];
                float v2 = (nB[c]   + na8) - 2.0f*acc[i][n][2];
                float v3 = (nB[c+1] + na8) - 2.0f*acc[i][n][3];
                *(float2*)(C + (size_t)r*Nc + c)     = make_float2(v0, v1);
                *(float2*)(C + (size_t)(r+8)*Nc + c) = make_float2(v2, v3);
            }
        }
    } else {
        #pragma unroll
        for (int i=0;i<2;i++){
            int r = row0 + wm*32 + i*16 + (lane>>2);
            #pragma unroll
            for (int n=0;n<8;n++){
                int c = col0 + wn*64 + n*8 + (lane&3)*2;
                *(float2*)(C + (size_t)r*Nc + c)     = make_float2(acc[i][n][0], acc[i][n][1]);
                *(float2*)(C + (size_t)(r+8)*Nc + c) = make_float2(acc[i][n][2], acc[i][n][3]);
            }
        }
    }
}

/* fused per-stage init: amin sentinel + cnt zero */
__global__ void k_stageinit(unsigned long long* a, float* cnt){
    int i = blockIdx.x*blockDim.x + threadIdx.x;
    if (i < 2*NB) a[i] = 0xFFFFFFFFFFFFFFFFull;
    if (i < 2*NM) cnt[i] = 0.f;
}

__global__ void k_hist(const unsigned long long* __restrict__ amin, float* __restrict__ cnt){
    int s = blockIdx.y;
    int b = blockIdx.x*blockDim.x + threadIdx.x;
    int id = (int)(unsigned)(amin[s*NB + b] & 0xFFFFFFFFull);
    atomicAdd(cnt + s*NM + id, 1.0f);
}

__global__ void k_perp(const float* __restrict__ cnt, float* __restrict__ out_perp, int stage){
    int s = blockIdx.x, t = threadIdx.x;
    float acc = 0.f;
    for (int m=t;m<NM;m+=256){
        float avg = cnt[s*NM+m] * (1.0f/(float)NB);
        acc += avg * logf(avg + 1e-10f);
    }
    acc = blockAllReduceSum(acc);
    if (t==0) out_perp[stage*2 + s] = expf(-acc);
}

__global__ void k_update(const float* __restrict__ E, const unsigned long long* __restrict__ amin,
                         float* __restrict__ res, float* __restrict__ q,
                         float* __restrict__ out_sem, int stage){
    int s = blockIdx.y, b = blockIdx.x, t = threadIdx.x;
    int id = (int)(unsigned)(amin[s*NB + b] & 0xFFFFFFFFull);
    float e = E[(size_t)id*ND + t];
    size_t o = (size_t)s*NBD + (size_t)b*ND + t;
    res[o] -= e;
    q[o]   += e;
    if (t==0) out_sem[(size_t)s*NB*NK + (size_t)b*NK + stage] = (float)id;
}

__global__ void k_softmax(const float* __restrict__ dist,
                          __nv_bfloat16* __restrict__ X, __nv_bfloat16* __restrict__ Y){
    int s = blockIdx.y, b = blockIdx.x, t = threadIdx.x;
    const float* row = dist + ((size_t)s*NB + b)*NM;
    float z[32];
    float mx = -INFINITY;
    #pragma unroll
    for (int i=0;i<32;i++){
        float v = row[i*256 + t];
        v = -sqrtf(fmaxf(v, 0.f));
        z[i] = v;
        mx = fmaxf(mx, v);
    }
    mx = blockAllReduceMax(mx);
    float sm = 0.f;
    #pragma unroll
    for (int i=0;i<32;i++){
        float e = expf(z[i]-mx);
        z[i] = e; sm += e;
    }
    sm = blockAllReduceSum(sm);
    __nv_bfloat16* xr = X + (size_t)b*(2*NM) + (size_t)s*NM;
    __nv_bfloat16* yr = Y + (size_t)b*(2*NM) + (size_t)(1-s)*NM;
    #pragma unroll
    for (int i=0;i<32;i++){
        int m = i*256 + t;
        float ph = z[i]/sm;
        xr[m] = __float2bfloat16(ph);
        yr[m] = __float2bfloat16(logf(ph + 1e-10f));
    }
}

__global__ void k_minred(const float* __restrict__ S, unsigned* mo){
    size_t NN = (size_t)NB*NB;
    float best = INFINITY;
    for (size_t n = (size_t)blockIdx.x*blockDim.x + threadIdx.x; n < NN;
         n += (size_t)gridDim.x*blockDim.x)
        best = fminf(best, S[n]);
    __shared__ float sh[256];
    sh[threadIdx.x]=best; __syncthreads();
    for (int o=128;o>0;o>>=1){
        if (threadIdx.x<o) sh[threadIdx.x]=fminf(sh[threadIdx.x],sh[threadIdx.x+o]);
        __syncthreads();
    }
    if (threadIdx.x==0) atomicMin(mo, f2ord(sh[0]));
}

__global__ void k_ratio(const float* __restrict__ S, const unsigned* mo, float* lr){
    int i = blockIdx.x, t = threadIdx.x;
    float Max = -ord2f(*mo);
    const float* row = S + (size_t)i*NB;
    float sm = 0.f;
    for (int j=t;j<NB;j+=256) sm += expf(row[j] + Max);
    sm = blockAllReduceSum(sm);
    if (t==0){
        float diag = expf(row[i] + Max);
        float ratio = diag / (sm + 1e-5f);
        atomicAdd(lr, logf(ratio));
    }
}

__global__ void k_msequant(const float* __restrict__ pcf, const float* __restrict__ plm,
                           const float* __restrict__ q, float* __restrict__ out,
                           float* mse){
    int n = blockIdx.x*blockDim.x + threadIdx.x;
    float p  = pcf[n], pl = plm[n];
    float qp = q[n],   ql = q[NBD + n];
    float qzp = p  + (qp - p);
    float qzl = pl + (ql - pl);
    out[n]        = qzp;
    out[NBD + n]  = qzl;
    float d0 = p - qzp, d1 = p - qzl, d2 = pl - qzl, d3 = pl - qzp;
    float s0 = blockAllReduceSum(d0*d0);
    float s1 = blockAllReduceSum(d1*d1);
    float s2 = blockAllReduceSum(d2*d2);
    float s3 = blockAllReduceSum(d3*d3);
    if (threadIdx.x==0){
        atomicAdd(mse+0, s0); atomicAdd(mse+1, s1);
        atomicAdd(mse+2, s2); atomicAdd(mse+3, s3);
    }
}

__global__ void k_final(const float* lr, const float* mse, float* out_loss){
    float Lc = -(*lr) / (float)NB;
    float inv = 1.0f/(float)NBD;
    float pcf_loss = 0.25f*2.0f*(mse[0]*inv) + 0.25f*(mse[1]*inv);
    float plm_loss = 0.25f*2.0f*(mse[2]*inv) + 0.25f*(mse[3]*inv);
    *out_loss = 0.5f*Lc + pcf_loss + plm_loss;
}

/* ------------------------------------------------------------------ */
extern "C" void kernel_launch(void* const* d_in, const int* in_sizes, int n_in,
                              void* d_out, int out_size){
    const float* pcf = (const float*)d_in[0];
    const float* plm = (const float*)d_in[1];
    const float* emb = (const float*)d_in[2];
    float* out = (float*)d_out;

    static int smem_set = 0;
    if (!smem_set){
        cudaFuncSetAttribute(k_tc, cudaFuncAttributeMaxDynamicSharedMemorySize, SMEM_BYTES);
        smem_set = 1;
    }

    void *p;
    float *res,*q,*normX,*normE,*dist,*S,*cnt,*lr,*mse;
    __nv_bfloat16 *Xb,*Yb,*Eb,*Xp;
    unsigned long long* amin;
    unsigned* mo;
    cudaGetSymbolAddress(&p, g_res);   res  = (float*)p;
    cudaGetSymbolAddress(&p, g_q);     q    = (float*)p;
    cudaGetSymbolAddress(&p, g_normX); normX= (float*)p;
    cudaGetSymbolAddress(&p, g_normE); normE= (float*)p;
    cudaGetSymbolAddress(&p, g_dist);  dist = (float*)p;
    cudaGetSymbolAddress(&p, g_Eb);    Eb   = (__nv_bfloat16*)p;
    cudaGetSymbolAddress(&p, g_Xp);    Xp   = (__nv_bfloat16*)p;
    cudaGetSymbolAddress(&p, g_Xb);    Xb   = (__nv_bfloat16*)p;
    cudaGetSymbolAddress(&p, g_Yb);    Yb   = (__nv_bfloat16*)p;
    cudaGetSymbolAddress(&p, g_S);     S    = (float*)p;
    cudaGetSymbolAddress(&p, g_amin);  amin = (unsigned long long*)p;
    cudaGetSymbolAddress(&p, g_cnt);   cnt  = (float*)p;
    cudaGetSymbolAddress(&p, g_minord);mo   = (unsigned*)p;
    cudaGetSymbolAddress(&p, g_lr);    lr   = (float*)p;
    cudaGetSymbolAddress(&p, g_mse);   mse  = (float*)p;

    /* output layout: quantized [2,B,D] | loss | sem_ids [2,B,K] | perp [K,2] */
    float* out_loss = out + (size_t)2*NBD;
    float* out_sem  = out_loss + 1;
    float* out_perp = out_sem + (size_t)2*NB*NK;

    k_init<<<(2*NBD+255)/256, 256>>>(pcf, plm, res, q, mo, lr, mse);
    k_splitB<<<NK*NM, 128>>>(emb, Eb);
    k_rownorm<<<NK*NM, 128>>>(emb, normE);
    k_rownorm<<<NB,128>>>(pcf, normX);
    k_rownorm<<<NB,128>>>(plm, normX+NB);
    k_splitA<<<2*NB, 128>>>(res, Xp);

    /* cmcm: only last stage's Lcmcm survives; ORIGINAL inputs + E3.
       z batches pcf/plm halves. */
    const __nv_bfloat16* Eb3 = Eb + (size_t)3*NM*KS6;
    k_tc<<<dim3(NM/BN, NB/BM, 2), 256, SMEM_BYTES>>>(
        Xp, Eb3, dist, KS6, NM, normX, normE+3*NM, (unsigned long long*)0, 1);
    k_softmax<<<dim3(NB,2), 256>>>(dist, Xb, Yb);
    k_tc<<<dim3(NB/BN, NB/BM, 1), 256, SMEM_BYTES>>>(
        Xb, Yb, S, 2*NM, NB, (const float*)0, (const float*)0, (unsigned long long*)0, 0);

    /* residual VQ stages: 6-term split bf16 dist GEMM with fused argmin */
    for (int st=0; st<NK; ++st){
        const float* E = emb + (size_t)st*NM*ND;
        const __nv_bfloat16* Ebs = Eb + (size_t)st*NM*KS6;
        if (st > 0){
            k_rownorm<<<NB,128>>>(res,      normX);
            k_rownorm<<<NB,128>>>(res+NBD,  normX+NB);
            k_splitA<<<2*NB, 128>>>(res, Xp);
        }
        k_stageinit<<<(2*NM+255)/256, 256>>>(amin, cnt);
        k_tc<<<dim3(NM/BN, NB/BM, 2), 256, SMEM_BYTES>>>(
            Xp, Ebs, (float*)0, KS6, NM, normX, normE+st*NM, amin, 2);
        k_hist<<<dim3(NB/256,2),256>>>(amin, cnt);
        k_perp<<<2,256>>>(cnt, out_perp, st);
        k_update<<<dim3(NB,2),128>>>(E, amin, res, q, out_sem, st);
    }

    /* cmcm loss reductions */
    k_minred<<<4096,256>>>(S, mo);
    k_ratio<<<NB,256>>>(S, mo, lr);
    k_msequant<<<NBD/256,256>>>(pcf, plm, q, out, mse);
    k_final<<<1,1>>>(lr, mse, out_loss);
}